// round 1
// baseline (speedup 1.0000x reference)
#include <cuda_runtime.h>

#define THREADS      512
#define PTS_PER_BLK  64
#define ACOLS        256      // 4 components * 64 points
#define HID          128
#define DIMX         39
#define NLAYERS      6

// shared: A[128][256] + W[128][128] + Ww[384] + Wv[384]
#define SMEM_FLOATS  (HID*ACOLS + HID*HID + 384 + 384)
#define SMEM_BYTES   (SMEM_FLOATS * 4)

// ---------------------------------------------------------------- fp32x2 FMA
__device__ __forceinline__ float2 ffma2(float2 a, float2 b, float2 c) {
    union U { float2 f; unsigned long long u; };
    U A, B, C, D;
    A.f = a; B.f = b; C.f = c;
    asm("fma.rn.f32x2 %0, %1, %2, %3;" : "=l"(D.u) : "l"(A.u), "l"(B.u), "l"(C.u));
    return D.f;
}

// ---------------------------------------------------------------- dual numbers (value + 3 tangents)
struct Dn { float v, x, y, z; };
__device__ __forceinline__ Dn dmk(float v)               { return Dn{v, 0.f, 0.f, 0.f}; }
__device__ __forceinline__ Dn dadd(const Dn& a, const Dn& b) { return Dn{a.v+b.v, a.x+b.x, a.y+b.y, a.z+b.z}; }
__device__ __forceinline__ Dn dsub(const Dn& a, const Dn& b) { return Dn{a.v-b.v, a.x-b.x, a.y-b.y, a.z-b.z}; }
__device__ __forceinline__ Dn dneg(const Dn& a)          { return Dn{-a.v, -a.x, -a.y, -a.z}; }
__device__ __forceinline__ Dn dmul(const Dn& a, const Dn& b) {
    return Dn{a.v*b.v,
              fmaf(a.v, b.x, a.x*b.v),
              fmaf(a.v, b.y, a.y*b.v),
              fmaf(a.v, b.z, a.z*b.v)};
}
__device__ __forceinline__ Dn dsqrt(const Dn& a) {
    float s = sqrtf(a.v); float h = 0.5f / s;
    return Dn{s, a.x*h, a.y*h, a.z*h};
}
__device__ __forceinline__ Dn drcp(const Dn& a) {
    float r = 1.f / a.v; float m = -r*r;
    return Dn{r, a.x*m, a.y*m, a.z*m};
}
__device__ __forceinline__ Dn dsin(const Dn& a) {
    float s = sinf(a.v), c = cosf(a.v);
    return Dn{s, c*a.x, c*a.y, c*a.z};
}
__device__ __forceinline__ Dn dcos(const Dn& a) {
    float s = sinf(a.v), c = cosf(a.v);
    return Dn{c, -s*a.x, -s*a.y, -s*a.z};
}

// ---------------------------------------------------------------- one MLP layer: GEMM(128 x K x 256) + bias + activation
// out[i, col] = act( sum_k W[i,k] * A[k, col] + b[i] )  (bias on value col only,
// tangent cols scaled by act'(pre) of their point's value col)
template<int K, int WS>
__device__ __forceinline__ void mlp_layer(float* sA, const float* sW,
                                          const float* __restrict__ bias,
                                          int i0, int j0, float slope)
{
    float2 acc[8][4];
    #pragma unroll
    for (int i = 0; i < 8; ++i)
        #pragma unroll
        for (int jp = 0; jp < 4; ++jp) acc[i][jp] = make_float2(0.f, 0.f);

    #pragma unroll 4
    for (int k = 0; k < K; ++k) {
        float4 a0 = *(const float4*)(sA + k * ACOLS + j0);
        float4 a1 = *(const float4*)(sA + k * ACOLS + j0 + 4);
        float2 b0 = make_float2(a0.x, a0.y);
        float2 b1 = make_float2(a0.z, a0.w);
        float2 b2 = make_float2(a1.x, a1.y);
        float2 b3 = make_float2(a1.z, a1.w);
        #pragma unroll
        for (int i = 0; i < 8; ++i) {
            float wv = sW[(i0 + i) * WS + k];
            float2 w2 = make_float2(wv, wv);
            acc[i][0] = ffma2(w2, b0, acc[i][0]);
            acc[i][1] = ffma2(w2, b1, acc[i][1]);
            acc[i][2] = ffma2(w2, b2, acc[i][2]);
            acc[i][3] = ffma2(w2, b3, acc[i][3]);
        }
    }
    __syncthreads();   // all reads of sA/sW complete before overwrite / W reload
    #pragma unroll
    for (int i = 0; i < 8; ++i) {
        float b = bias[i0 + i];
        float v0 = acc[i][0].x + b;
        float m0 = v0 > 0.f ? 1.f : slope;
        *(float4*)(sA + (i0 + i) * ACOLS + j0) =
            make_float4(m0 * v0, m0 * acc[i][0].y, m0 * acc[i][1].x, m0 * acc[i][1].y);
        float v1 = acc[i][2].x + b;
        float m1 = v1 > 0.f ? 1.f : slope;
        *(float4*)(sA + (i0 + i) * ACOLS + j0 + 4) =
            make_float4(m1 * v1, m1 * acc[i][2].y, m1 * acc[i][3].x, m1 * acc[i][3].y);
    }
}

// ----------------------------------------------------------------
__global__ __launch_bounds__(THREADS, 1)
void nerfies_kernel(const float* __restrict__ x,
                    const float* __restrict__ Win,
                    const float* __restrict__ bin,
                    const float* __restrict__ Ws,
                    const float* __restrict__ bs,
                    const float* __restrict__ Ww,
                    const float* __restrict__ bw,
                    const float* __restrict__ Wv,
                    const float* __restrict__ bv,
                    const int*   __restrict__ iter,
                    float* __restrict__ out,
                    int N)
{
    extern __shared__ float smem[];
    float* sA  = smem;                         // 128 x 256
    float* sW  = smem + HID * ACOLS;           // 128 x 128
    float* sWw = sW + HID * HID;               // 3 x 128
    float* sWv = sWw + 384;                    // 3 x 128

    const int tid = threadIdx.x;
    const int p0  = blockIdx.x * PTS_PER_BLK;

    // annealing params (PI literal = 3.14, N_ANNEAL = 0.6*5000 = 3000, M = 6, K0 = -3)
    const float itf = (float)(*iter);
    const float aa  = 6.0f * itf / 3000.0f;

    // ---- positional encoding + its analytic derivative into sA ----
    // row layout f in [0,39): f<3 -> pos passthrough; f>=3: g=f-3, c=g/12, t=(g%12)/6, j=g%6
    for (int idx = tid; idx < PTS_PER_BLK * DIMX; idx += THREADS) {
        int p = idx / DIMX, f = idx % DIMX;
        int gp = p0 + p;
        float val = 0.f, d0 = 0.f, d1 = 0.f, d2 = 0.f;
        if (gp < N) {
            if (f < 3) {
                val = x[gp * 3 + f];
                if (f == 0) d0 = 1.f; else if (f == 1) d1 = 1.f; else d2 = 1.f;
            } else {
                int g = f - 3;
                int c = g / 12;
                int rem = g % 12;
                int t = rem / 6;
                int j = rem % 6;
                float wj = (1.0f - cosf(fminf(fmaxf(aa - (float)j, 0.f), 1.f) * 3.14f)) * 0.5f;
                float mj = exp2f((float)(j - 3)) * 3.14f;
                float xc = x[gp * 3 + c];
                float ang = xc * mj;
                float sv = sinf(ang), cv = cosf(ang);
                float dv;
                if (t == 0) { val = sv * wj; dv =  cv * mj * wj; }
                else        { val = cv * wj; dv = -sv * mj * wj; }
                if (c == 0) d0 = dv; else if (c == 1) d1 = dv; else d2 = dv;
            }
        }
        *(float4*)(sA + f * ACOLS + 4 * p) = make_float4(val, d0, d1, d2);
    }
    // load W_in [128 x 39] and head weights
    for (int idx = tid; idx < HID * DIMX; idx += THREADS) sW[idx] = Win[idx];
    for (int idx = tid; idx < 384; idx += THREADS) { sWw[idx] = Ww[idx]; sWv[idx] = Wv[idx]; }
    __syncthreads();

    const int ty = tid >> 5, tx = tid & 31;
    const int i0 = ty * 8, j0 = tx * 8;

    // input layer: leaky_relu(0.01)
    mlp_layer<DIMX, DIMX>(sA, sW, bin, i0, j0, 0.01f);

    // 6 hidden layers: relu
    for (int l = 0; l < NLAYERS; ++l) {
        // safe to overwrite sW: previous layer's reads completed at its internal sync
        const float4* wg = (const float4*)(Ws + l * HID * HID);
        for (int idx = tid; idx < HID * HID / 4; idx += THREADS)
            ((float4*)sW)[idx] = wg[idx];
        __syncthreads();   // W loaded + previous writeback visible
        mlp_layer<HID, HID>(sA, sW, bs + l * HID, i0, j0, 0.f);
    }
    __syncthreads();       // final activations visible to tail

    // ---- tail: heads (128->3 twice, with tangents), SE(3) exp, output ----
    const int p = tid >> 3;       // point within block
    const int r = tid & 7;        // 8 threads per point split k-range
    const int gp = p0 + p;

    float aw[3][4], av[3][4];
    #pragma unroll
    for (int a = 0; a < 3; ++a)
        #pragma unroll
        for (int c = 0; c < 4; ++c) { aw[a][c] = 0.f; av[a][c] = 0.f; }

    #pragma unroll 4
    for (int kk = 0; kk < 16; ++kk) {
        int k = r * 16 + kk;
        float4 f4 = *(const float4*)(sA + k * ACOLS + 4 * p);
        #pragma unroll
        for (int a = 0; a < 3; ++a) {
            float ww = sWw[a * HID + k];
            float wv = sWv[a * HID + k];
            aw[a][0] = fmaf(ww, f4.x, aw[a][0]);
            aw[a][1] = fmaf(ww, f4.y, aw[a][1]);
            aw[a][2] = fmaf(ww, f4.z, aw[a][2]);
            aw[a][3] = fmaf(ww, f4.w, aw[a][3]);
            av[a][0] = fmaf(wv, f4.x, av[a][0]);
            av[a][1] = fmaf(wv, f4.y, av[a][1]);
            av[a][2] = fmaf(wv, f4.z, av[a][2]);
            av[a][3] = fmaf(wv, f4.w, av[a][3]);
        }
    }
    // reduce the 8 partial sums per point (lanes form groups of 8)
    #pragma unroll
    for (int off = 4; off >= 1; off >>= 1) {
        #pragma unroll
        for (int a = 0; a < 3; ++a)
            #pragma unroll
            for (int c = 0; c < 4; ++c) {
                aw[a][c] += __shfl_down_sync(0xffffffffu, aw[a][c], off, 8);
                av[a][c] += __shfl_down_sync(0xffffffffu, av[a][c], off, 8);
            }
    }

    if (r == 0 && gp < N) {
        Dn wr[3], vr[3];
        #pragma unroll
        for (int a = 0; a < 3; ++a) {
            wr[a] = Dn{aw[a][0] + bw[a], aw[a][1], aw[a][2], aw[a][3]};
            vr[a] = Dn{av[a][0] + bv[a], av[a][1], av[a][2], av[a][3]};
        }
        Dn n2 = dadd(dadd(dmul(wr[0], wr[0]), dmul(wr[1], wr[1])), dmul(wr[2], wr[2]));
        Dn th = dsqrt(n2);
        Dn rt = drcp(th);
        Dn w0 = dmul(wr[0], rt), w1 = dmul(wr[1], rt), w2 = dmul(wr[2], rt);
        Dn v0 = dmul(vr[0], rt), v1 = dmul(vr[1], rt), v2 = dmul(vr[2], rt);
        Dn s  = dsin(th), c = dcos(th);
        Dn oc = dsub(dmk(1.f), c);
        Dn ts = dsub(th, s);

        Dn Wm[3][3] = {
            { dmk(0.f), dneg(w2),  w1       },
            { w2,       dmk(0.f),  dneg(w0) },
            { dneg(w1), w0,        dmk(0.f) } };
        Dn W2[3][3];
        #pragma unroll
        for (int i = 0; i < 3; ++i)
            #pragma unroll
            for (int j = 0; j < 3; ++j)
                W2[i][j] = dadd(dadd(dmul(Wm[i][0], Wm[0][j]),
                                     dmul(Wm[i][1], Wm[1][j])),
                                dmul(Wm[i][2], Wm[2][j]));
        Dn R[3][3], G[3][3];
        #pragma unroll
        for (int i = 0; i < 3; ++i)
            #pragma unroll
            for (int j = 0; j < 3; ++j) {
                Dn rr = dadd(dmul(s, Wm[i][j]), dmul(oc, W2[i][j]));
                if (i == j) rr.v += 1.f;
                R[i][j] = rr;
                Dn gg = dadd(dmul(oc, Wm[i][j]), dmul(ts, W2[i][j]));
                if (i == j) gg = dadd(gg, th);
                G[i][j] = gg;
            }
        Dn tvec[3];
        #pragma unroll
        for (int i = 0; i < 3; ++i)
            tvec[i] = dadd(dadd(dmul(G[i][0], v0), dmul(G[i][1], v1)), dmul(G[i][2], v2));

        float xv0 = x[gp * 3 + 0], xv1 = x[gp * 3 + 1], xv2 = x[gp * 3 + 2];
        Dn xd[3] = { Dn{xv0, 1.f, 0.f, 0.f}, Dn{xv1, 0.f, 1.f, 0.f}, Dn{xv2, 0.f, 0.f, 1.f} };

        float* J = out + (size_t)N * 3 + (size_t)gp * 9;
        #pragma unroll
        for (int i = 0; i < 3; ++i) {
            Dn o = dadd(tvec[i],
                        dadd(dadd(dmul(R[i][0], xd[0]), dmul(R[i][1], xd[1])),
                             dmul(R[i][2], xd[2])));
            out[gp * 3 + i] = o.v;
            J[i * 3 + 0] = o.x;
            J[i * 3 + 1] = o.y;
            J[i * 3 + 2] = o.z;
        }
    }
}

// ----------------------------------------------------------------
extern "C" void kernel_launch(void* const* d_in, const int* in_sizes, int n_in,
                              void* d_out, int out_size) {
    const float* x   = (const float*)d_in[0];
    const float* Win = (const float*)d_in[1];
    const float* bin = (const float*)d_in[2];
    const float* Ws  = (const float*)d_in[3];
    const float* bs  = (const float*)d_in[4];
    const float* Ww  = (const float*)d_in[5];
    const float* bw  = (const float*)d_in[6];
    const float* Wv  = (const float*)d_in[7];
    const float* bv  = (const float*)d_in[8];
    const int*   it  = (const int*)d_in[9];
    float* out = (float*)d_out;

    int N = in_sizes[0] / 3;
    int grid = (N + PTS_PER_BLK - 1) / PTS_PER_BLK;

    cudaFuncSetAttribute(nerfies_kernel,
                         cudaFuncAttributeMaxDynamicSharedMemorySize, SMEM_BYTES);
    nerfies_kernel<<<grid, THREADS, SMEM_BYTES>>>(x, Win, bin, Ws, bs, Ww, bw, Wv, bv,
                                                  it, out, N);
}